// round 10
// baseline (speedup 1.0000x reference)
#include <cuda_runtime.h>

// Conv2D valid cross-correlation: x[4096,4096] fp32 * w[15,15] + bias -> out[4082,4082]
//
// v9: v5 (cmem scalar weights, RY=4) + software-pipelined input rows.
//  Model: FFMA2 dual-issues (fma+alu slot) -> ceiling 0.5/SMSP/cyc. v5 ran at
//  0.37 with ~16% idle issue slots that more occupancy did NOT fill (v4 vs v5)
//  -> per-row LDS dependency stall. Fix: ping-pong ev buffers, prefetch row
//  r+1's LDS.128s (asm volatile, pinned) before row r's 240 FFMA2.
//  - weights: __constant__ u64 (w,w) pairs, array-indexed (proven LDCU path;
//    v8's pointer-cast variant broke const space -> never again).
//  - block 256 thr, tile 128x * 64y, thread 8x * 4y outputs.

#define Hd 4096
#define Wd 4096
#define KHd 15
#define KWd 15
#define OHd (Hd - KHd + 1)   // 4082
#define OWd (Wd - KWd + 1)   // 4082

#define BXo 128
#define BYo 64
#define RY 4
#define TILE_ROWS (BYo + KHd - 1)   // 78
#define SSTR 144                     // floats per smem row
#define ROWB (SSTR * 4)              // 576 bytes per smem row

typedef unsigned long long u64;

__constant__ u64 c_w2[KHd * KWd];    // (w,w) duplicated pairs, row-major 15x15

__device__ __forceinline__ u64 pack2(float lo, float hi) {
    u64 r;
    asm("mov.b64 %0, {%1, %2};" : "=l"(r) : "f"(lo), "f"(hi));
    return r;
}

__device__ __forceinline__ u64 fma2(u64 a, u64 b, u64 c) {
    u64 d;
    asm("fma.rn.f32x2 %0, %1, %2, %3;" : "=l"(d) : "l"(a), "l"(b), "l"(c));
    return d;
}

// odd pair = {hi(a), lo(b)} : exactly 2 SASS MOVs
__device__ __forceinline__ u64 mkodd(u64 a, u64 b) {
    u64 r;
    asm("{\n\t"
        ".reg .b32 al, ah, bl, bh;\n\t"
        "mov.b64 {al, ah}, %1;\n\t"
        "mov.b64 {bl, bh}, %2;\n\t"
        "mov.b64 %0, {ah, bl};\n\t"
        "}" : "=l"(r) : "l"(a), "l"(b));
    return r;
}

// Pinned prefetch of one smem row: 6x LDS.128 into ev (12 even pairs).
__device__ __forceinline__ void ldrow(u64 ev[12], unsigned int saddr) {
#pragma unroll
    for (int i = 0; i < 6; ++i)
        asm volatile("ld.shared.v2.u64 {%0, %1}, [%2];"
                     : "=l"(ev[2 * i]), "=l"(ev[2 * i + 1])
                     : "r"(saddr + 16u * i));
}

// Derive 10 odd pairs from even pairs (2 MOVs each).
__device__ __forceinline__ void mkods(u64 od[10], const u64 ev[12]) {
#pragma unroll
    for (int j = 0; j < 10; ++j)
        od[j] = mkodd(ev[j], ev[j + 1]);
}

// One ky-row of the stencil applied to 4 output pairs of one output row.
// wrow: index into c_w2 (warp-uniform -> LDCU / UR operand).
__device__ __forceinline__ void conv_row(u64 acc[4], int wbase,
                                         const u64 ev[12], const u64 od[10]) {
#pragma unroll
    for (int kx = 0; kx < KWd; ++kx) {
        u64 w2 = c_w2[wbase + kx];
        if ((kx & 1) == 0) {
#pragma unroll
            for (int p = 0; p < 4; ++p)
                acc[p] = fma2(ev[(kx >> 1) + p], w2, acc[p]);
        } else {
#pragma unroll
            for (int p = 0; p < 4; ++p)
                acc[p] = fma2(od[(kx >> 1) + p], w2, acc[p]);
        }
    }
}

__global__ __launch_bounds__(256, 3)
void conv2d_f32x2_kernel(const float* __restrict__ x,
                         const float* __restrict__ bias,
                         float* __restrict__ out) {
    __shared__ float s_in[TILE_ROWS * SSTR];   // 44928 B

    const int tid = threadIdx.x;
    const int tx0 = blockIdx.x * BXo;
    const int ty0 = blockIdx.y * BYo;

    // Stage input tile: 78 rows x 144 floats.
    for (int s = tid; s < TILE_ROWS * 36; s += 256) {
        int rr = s / 36;
        int cc = (s - rr * 36) * 4;
        int gy = ty0 + rr;
        int gx = tx0 + cc;
        float4 v;
        if (gy < Hd && gx + 3 < Wd) {
            v = *(const float4*)(x + (size_t)gy * Wd + gx);
        } else {
            v.x = (gy < Hd && gx + 0 < Wd) ? x[(size_t)gy * Wd + gx + 0] : 0.f;
            v.y = (gy < Hd && gx + 1 < Wd) ? x[(size_t)gy * Wd + gx + 1] : 0.f;
            v.z = (gy < Hd && gx + 2 < Wd) ? x[(size_t)gy * Wd + gx + 2] : 0.f;
            v.w = (gy < Hd && gx + 3 < Wd) ? x[(size_t)gy * Wd + gx + 3] : 0.f;
        }
        *(float4*)&s_in[rr * SSTR + cc] = v;
    }
    __syncthreads();

    const int tx = tid & 15;
    const int ty = tid >> 4;
    const int oxl = tx * 8;        // 8 outputs in x
    const int oyl = ty * RY;       // 4 outputs in y

    const float b = bias[0];
    const u64 b2 = pack2(b, b);
    u64 acc[RY][4];
#pragma unroll
    for (int j = 0; j < RY; ++j)
#pragma unroll
        for (int p = 0; p < 4; ++p) acc[j][p] = b2;

    // Shared-space byte address of this thread's row window.
    unsigned int sa;
    {
        const float* sbase = &s_in[oyl * SSTR + oxl];
        asm("{ .reg .u64 t; cvta.to.shared.u64 t, %1; cvt.u32.u64 %0, t; }"
            : "=r"(sa) : "l"(sbase));
    }

    u64 evA[12], evB[12], od[10];

    // ---- Prologue (rows 0..2), prefetch one row ahead throughout ----
    ldrow(evA, sa + 0 * ROWB);

    ldrow(evB, sa + 1 * ROWB);
    mkods(od, evA);
    conv_row(acc[0], 0 * KWd, evA, od);                 // row 0

    ldrow(evA, sa + 2 * ROWB);
    mkods(od, evB);
    conv_row(acc[0], 1 * KWd, evB, od);                 // row 1
    conv_row(acc[1], 0 * KWd, evB, od);

    ldrow(evB, sa + 3 * ROWB);
    mkods(od, evA);
    conv_row(acc[0], 2 * KWd, evA, od);                 // row 2
    conv_row(acc[1], 1 * KWd, evA, od);
    conv_row(acc[2], 0 * KWd, evA, od);

    // ---- Steady: rows 3..14 (x2 unrolled ping-pong; evB holds row r) ----
#pragma unroll 1
    for (int r = 3; r <= 13; r += 2) {
        ldrow(evA, sa + (r + 1) * ROWB);
        mkods(od, evB);
        conv_row(acc[0], (r    ) * KWd, evB, od);       // row r
        conv_row(acc[1], (r - 1) * KWd, evB, od);
        conv_row(acc[2], (r - 2) * KWd, evB, od);
        conv_row(acc[3], (r - 3) * KWd, evB, od);

        ldrow(evB, sa + (r + 2) * ROWB);
        mkods(od, evA);
        conv_row(acc[0], (r + 1) * KWd, evA, od);       // row r+1
        conv_row(acc[1], (r    ) * KWd, evA, od);
        conv_row(acc[2], (r - 1) * KWd, evA, od);
        conv_row(acc[3], (r - 2) * KWd, evA, od);
    }
    // evB now holds row 15.

    // ---- Epilogue (rows 15..17) ----
    ldrow(evA, sa + 16 * ROWB);
    mkods(od, evB);
    conv_row(acc[1], 14 * KWd, evB, od);                // row 15
    conv_row(acc[2], 13 * KWd, evB, od);
    conv_row(acc[3], 12 * KWd, evB, od);

    ldrow(evB, sa + 17 * ROWB);
    mkods(od, evA);
    conv_row(acc[2], 14 * KWd, evA, od);                // row 16
    conv_row(acc[3], 13 * KWd, evA, od);

    mkods(od, evB);
    conv_row(acc[3], 14 * KWd, evB, od);                // row 17

    // Store: even-aligned 8B pairs; OW=4082 even -> pairs never straddle rows.
    const int oxg = tx0 + oxl;
#pragma unroll
    for (int j = 0; j < RY; ++j) {
        int oy = ty0 + oyl + j;
        if (oy < OHd) {
            float* orow = out + (size_t)oy * OWd;
#pragma unroll
            for (int p = 0; p < 4; ++p) {
                int ox = oxg + 2 * p;
                if (ox < OWd) {
                    *(u64*)(orow + ox) = acc[j][p];
                }
            }
        }
    }
}

extern "C" void kernel_launch(void* const* d_in, const int* in_sizes, int n_in,
                              void* d_out, int out_size) {
    const float* x    = (const float*)d_in[0];
    const float* wt   = (const float*)d_in[1];
    const float* bias = (const float*)d_in[2];
    float* out        = (float*)d_out;

    // Build (w,w) u64 pairs in __constant__ memory (async D2D, graph-capturable).
    void* cw_addr = nullptr;
    cudaGetSymbolAddress(&cw_addr, c_w2);
    cudaMemcpy2DAsync(cw_addr, 8, wt, 4, 4, KHd * KWd,
                      cudaMemcpyDeviceToDevice, 0);
    cudaMemcpy2DAsync((char*)cw_addr + 4, 8, wt, 4, 4, KHd * KWd,
                      cudaMemcpyDeviceToDevice, 0);

    dim3 grid((OWd + BXo - 1) / BXo, (OHd + BYo - 1) / BYo);  // (32, 64)
    conv2d_f32x2_kernel<<<grid, 256>>>(x, bias, out);
}